// round 2
// baseline (speedup 1.0000x reference)
#include <cuda_runtime.h>
#include <cstdint>

#define NN 50000
#define FIN 128
#define HCC 256
#define EE 800000
#define BN_EPS 1e-5f

// ---------------- scratch (device globals; no allocation allowed) ----------------
__device__ float d_Y1[(size_t)NN * 512];   // [N,512]: cols 0..255 = lin part (+c), 256..511 = hW (+c)
__device__ float d_h1[(size_t)NN * HCC];   // layer-1 output
__device__ float d_als1[NN * 4];
__device__ float d_ald1[NN * 4];
__device__ float d_Y2[NN * 4];             // cols 0,1 = lin3 part (+c), 2,3 = hW2 (+c)
__device__ float d_als2[NN];
__device__ float d_ald2[NN];
__device__ int   d_src[EE];
__device__ int   d_dst[EE];
__device__ int   d_deg[NN];
__device__ int   d_rowptr[NN + 1];
__device__ int   d_wpos[NN];
__device__ int   d_ssrc[EE];               // src node per edge, sorted by dst
__device__ float d_sum1[FIN], d_sq1[FIN];
__device__ float d_sum3[HCC], d_sq3[HCC];
__device__ float d_W1eff[FIN * 512];
__device__ float d_c1[512];
__device__ float d_W2eff[HCC * 4];
__device__ float d_c2[4];
__device__ int   d_is64;

// ---------------- helpers ----------------
__device__ __forceinline__ float warpMax(float v) {
    #pragma unroll
    for (int o = 16; o; o >>= 1) v = fmaxf(v, __shfl_xor_sync(0xffffffffu, v, o));
    return v;
}
__device__ __forceinline__ float warpSum(float v) {
    #pragma unroll
    for (int o = 16; o; o >>= 1) v += __shfl_xor_sync(0xffffffffu, v, o);
    return v;
}
__device__ __forceinline__ float lrelu(float x) { return x > 0.f ? x : 0.2f * x; }

// ---------------- kernels ----------------
__global__ void k_zero() {
    int i = blockIdx.x * blockDim.x + threadIdx.x;
    if (i < NN) d_deg[i] = 0;
    if (i < FIN) { d_sum1[i] = 0.f; d_sq1[i] = 0.f; }
    if (i < HCC) { d_sum3[i] = 0.f; d_sq3[i] = 0.f; }
    if (i == 0) d_is64 = 1;
}

// dtype probe: read first EE 8-byte words (safe span under either dtype).
// int64 data -> all values in [0,NN). int32 data -> packed pairs look huge.
__global__ void k_detect(const long long* __restrict__ p) {
    int stride = gridDim.x * blockDim.x;
    for (int e = blockIdx.x * blockDim.x + threadIdx.x; e < EE; e += stride) {
        long long v = p[e];
        if (v < 0 || v >= NN) { d_is64 = 0; return; }
    }
}

__global__ void k_decode(const void* __restrict__ ei) {
    int stride = gridDim.x * blockDim.x;
    bool is64 = (d_is64 != 0);
    if (is64) {
        const long long* p = (const long long*)ei;
        for (int e = blockIdx.x * blockDim.x + threadIdx.x; e < EE; e += stride) {
            d_src[e] = (int)p[e];
            d_dst[e] = (int)p[EE + e];
        }
    } else {
        const int* p = (const int*)ei;
        for (int e = blockIdx.x * blockDim.x + threadIdx.x; e < EE; e += stride) {
            d_src[e] = p[e];
            d_dst[e] = p[EE + e];
        }
    }
}

__global__ void k_colstats_x(const float* __restrict__ X) {
    int c = threadIdx.x;                      // blockDim = 128
    float s = 0.f, q = 0.f;
    for (int r = blockIdx.x; r < NN; r += gridDim.x) {
        float v = X[(size_t)r * FIN + c];
        s += v; q += v * v;
    }
    atomicAdd(&d_sum1[c], s);
    atomicAdd(&d_sq1[c], q);
}

__global__ void k_colstats_h1() {
    int c = threadIdx.x;                      // blockDim = 256
    float s = 0.f, q = 0.f;
    for (int r = blockIdx.x; r < NN; r += gridDim.x) {
        float v = d_h1[(size_t)r * HCC + c];
        s += v; q += v * v;
    }
    atomicAdd(&d_sum3[c], s);
    atomicAdd(&d_sq3[c], q);
}

__global__ void k_hist() {
    int stride = gridDim.x * blockDim.x;
    for (int e = blockIdx.x * blockDim.x + threadIdx.x; e < EE; e += stride) {
        int dd = d_dst[e];
        if (dd >= 0 && dd < NN) atomicAdd(&d_deg[dd], 1);
    }
}

__global__ void k_scan() {                    // single block, 1024 threads
    __shared__ int tots[1024];
    int t = threadIdx.x;
    const int per = (NN + 1023) / 1024;       // 49
    int beg = t * per, end = min(beg + per, NN);
    int s = 0;
    for (int i = beg; i < end; i++) s += d_deg[i];
    tots[t] = s;
    __syncthreads();
    for (int off = 1; off < 1024; off <<= 1) {
        int v = (t >= off) ? tots[t - off] : 0;
        __syncthreads();
        tots[t] += v;
        __syncthreads();
    }
    int prefix = (t == 0) ? 0 : tots[t - 1];
    for (int i = beg; i < end; i++) {
        int dv = d_deg[i];
        d_rowptr[i] = prefix;
        d_wpos[i] = prefix;
        prefix += dv;
    }
    if (t == 1023) d_rowptr[NN] = prefix;
}

__global__ void k_scatter() {
    int stride = gridDim.x * blockDim.x;
    for (int e = blockIdx.x * blockDim.x + threadIdx.x; e < EE; e += stride) {
        int dd = d_dst[e];
        if (dd >= 0 && dd < NN) {
            int p = atomicAdd(&d_wpos[dd], 1);
            int sv = d_src[e];
            d_ssrc[p] = (sv >= 0 && sv < NN) ? sv : 0;
        }
    }
}

// fold BN1 into [lin1_W | g1_W]: W1eff[k,j] = s[k]*W, c1[j] = sum_k t[k]*W[k,j] (+ lin1_b for lin cols)
__global__ void k_fold1(const float* __restrict__ g, const float* __restrict__ b,
                        const float* __restrict__ lin1W, const float* __restrict__ lin1b,
                        const float* __restrict__ g1W) {
    __shared__ float ssc[FIN], tsh[FIN];
    int tid = threadIdx.x;                    // blockDim = 512
    if (tid < FIN) {
        float mu  = d_sum1[tid] * (1.f / NN);
        float var = d_sq1[tid] * (1.f / NN) - mu * mu;
        float sc  = rsqrtf(var + BN_EPS) * g[tid];
        ssc[tid] = sc;
        tsh[tid] = b[tid] - mu * sc;
    }
    __syncthreads();
    int j = tid;
    float acc = (j < 256) ? lin1b[j] : 0.f;
    for (int k = 0; k < FIN; k++) {
        float w = (j < 256) ? lin1W[k * 256 + j] : g1W[k * 256 + (j - 256)];
        acc += tsh[k] * w;
    }
    d_c1[j] = acc;
    for (int idx = tid; idx < FIN * 512; idx += 512) {
        int k = idx >> 9, jj = idx & 511;
        float w = (jj < 256) ? lin1W[k * 256 + jj] : g1W[k * 256 + (jj - 256)];
        d_W1eff[idx] = ssc[k] * w;
    }
}

// Y1[N,512] = x @ W1eff + c1    (64x64 tile, 256 threads, 4x4 microtile, K chunks of 32)
__global__ void k_gemm1(const float* __restrict__ A) {
    __shared__ float As[32][65];
    __shared__ float Bs[32][64];
    int tid = threadIdx.x;
    int row0 = blockIdx.y * 64, col0 = blockIdx.x * 64;
    int ty = tid >> 4, tx = tid & 15;
    float acc[4][4];
    #pragma unroll
    for (int u = 0; u < 4; u++)
        #pragma unroll
        for (int v = 0; v < 4; v++) acc[u][v] = 0.f;

    for (int k0 = 0; k0 < FIN; k0 += 32) {
        #pragma unroll
        for (int i = 0; i < 8; i++) {
            int idx = tid + i * 256;
            int r = idx >> 5, c = idx & 31;
            int gr = row0 + r;
            As[c][r] = (gr < NN) ? A[(size_t)gr * FIN + k0 + c] : 0.f;
        }
        #pragma unroll
        for (int i = 0; i < 8; i++) {
            int idx = tid + i * 256;
            int r = idx >> 6, c = idx & 63;
            Bs[r][c] = d_W1eff[(k0 + r) * 512 + col0 + c];
        }
        __syncthreads();
        #pragma unroll
        for (int kk = 0; kk < 32; kk++) {
            float a[4], bb[4];
            #pragma unroll
            for (int u = 0; u < 4; u++) a[u] = As[kk][ty * 4 + u];
            #pragma unroll
            for (int v = 0; v < 4; v++) bb[v] = Bs[kk][tx * 4 + v];
            #pragma unroll
            for (int u = 0; u < 4; u++)
                #pragma unroll
                for (int v = 0; v < 4; v++) acc[u][v] += a[u] * bb[v];
        }
        __syncthreads();
    }
    #pragma unroll
    for (int u = 0; u < 4; u++) {
        int gr = row0 + ty * 4 + u;
        if (gr < NN) {
            #pragma unroll
            for (int v = 0; v < 4; v++) {
                int gc = col0 + tx * 4 + v;
                d_Y1[(size_t)gr * 512 + gc] = acc[u][v] + d_c1[gc];
            }
        }
    }
}

// attention logit projections: al_s[n,h] = sum_c hW[n,h*64+c]*a_src[h,c]
__global__ void k_alphas1(const float* __restrict__ asrc, const float* __restrict__ adst) {
    int w = (blockIdx.x * blockDim.x + threadIdx.x) >> 5;
    int lane = threadIdx.x & 31;
    if (w >= NN) return;
    const float* hw = d_Y1 + (size_t)w * 512 + 256;
    float as[4] = {0.f, 0.f, 0.f, 0.f}, ad[4] = {0.f, 0.f, 0.f, 0.f};
    #pragma unroll
    for (int jj = 0; jj < 8; jj++) {
        int j = lane + 32 * jj;
        float h = hw[j];
        as[jj >> 1] += h * asrc[j];
        ad[jj >> 1] += h * adst[j];
    }
    #pragma unroll
    for (int h = 0; h < 4; h++) { as[h] = warpSum(as[h]); ad[h] = warpSum(ad[h]); }
    if (lane == 0) {
        #pragma unroll
        for (int h = 0; h < 4; h++) { d_als1[w * 4 + h] = as[h]; d_ald1[w * 4 + h] = ad[h]; }
    }
}

// layer-1 edge aggregation + combine + relu -> h1. One warp per dst node, no atomics.
__global__ void k_edge1(const float* __restrict__ g1bias) {
    int w = (blockIdx.x * blockDim.x + threadIdx.x) >> 5;
    int lane = threadIdx.x & 31;
    if (w >= NN) return;
    int beg = d_rowptr[w], end = d_rowptr[w + 1];
    float acc[8];
    #pragma unroll
    for (int j = 0; j < 8; j++) acc[j] = 0.f;

    if (end > beg) {
        float4 adv = *(const float4*)(d_ald1 + w * 4);
        float ad[4] = {adv.x, adv.y, adv.z, adv.w};
        // pass 1: per-head max
        float m[4] = {-1e30f, -1e30f, -1e30f, -1e30f};
        for (int i = beg + lane; i < end; i += 32) {
            int s = d_ssrc[i];
            float4 av = *(const float4*)(d_als1 + s * 4);
            float e0 = lrelu(av.x + ad[0]); m[0] = fmaxf(m[0], e0);
            float e1 = lrelu(av.y + ad[1]); m[1] = fmaxf(m[1], e1);
            float e2 = lrelu(av.z + ad[2]); m[2] = fmaxf(m[2], e2);
            float e3 = lrelu(av.w + ad[3]); m[3] = fmaxf(m[3], e3);
        }
        #pragma unroll
        for (int h = 0; h < 4; h++) m[h] = warpMax(m[h]);
        // pass 2: per-head sum
        float ss[4] = {0.f, 0.f, 0.f, 0.f};
        for (int i = beg + lane; i < end; i += 32) {
            int s = d_ssrc[i];
            float4 av = *(const float4*)(d_als1 + s * 4);
            ss[0] += __expf(lrelu(av.x + ad[0]) - m[0]);
            ss[1] += __expf(lrelu(av.y + ad[1]) - m[1]);
            ss[2] += __expf(lrelu(av.z + ad[2]) - m[2]);
            ss[3] += __expf(lrelu(av.w + ad[3]) - m[3]);
        }
        float inv[4];
        #pragma unroll
        for (int h = 0; h < 4; h++) inv[h] = 1.f / (warpSum(ss[h]) + 1e-16f);
        // pass 3: weighted accumulation (whole warp per edge, coalesced 1KB gather)
        for (int i = beg; i < end; i++) {
            int s = d_ssrc[i];
            float4 av = *(const float4*)(d_als1 + s * 4);   // broadcast
            float wa[4];
            wa[0] = __expf(lrelu(av.x + ad[0]) - m[0]) * inv[0];
            wa[1] = __expf(lrelu(av.y + ad[1]) - m[1]) * inv[1];
            wa[2] = __expf(lrelu(av.z + ad[2]) - m[2]) * inv[2];
            wa[3] = __expf(lrelu(av.w + ad[3]) - m[3]) * inv[3];
            const float* hwrow = d_Y1 + (size_t)s * 512 + 256;
            #pragma unroll
            for (int jj = 0; jj < 8; jj++)
                acc[jj] += hwrow[lane + 32 * jj] * wa[jj >> 1];
        }
    }
    const float* linrow = d_Y1 + (size_t)w * 512;
    #pragma unroll
    for (int jj = 0; jj < 8; jj++) {
        int col = lane + 32 * jj;
        float v = acc[jj] + linrow[col] + g1bias[col];
        d_h1[(size_t)w * HCC + col] = v > 0.f ? v : 0.f;
    }
}

// fold BN3 into [lin3_W | g2_W]
__global__ void k_fold2(const float* __restrict__ g, const float* __restrict__ b,
                        const float* __restrict__ lin3W, const float* __restrict__ lin3b,
                        const float* __restrict__ g2W) {
    __shared__ float ssc[HCC], tsh[HCC];
    int tid = threadIdx.x;                    // blockDim = 256
    float mu  = d_sum3[tid] * (1.f / NN);
    float var = d_sq3[tid] * (1.f / NN) - mu * mu;
    float sc  = rsqrtf(var + BN_EPS) * g[tid];
    ssc[tid] = sc;
    tsh[tid] = b[tid] - mu * sc;
    __syncthreads();
    #pragma unroll
    for (int j = 0; j < 4; j++) {
        float w = (j < 2) ? lin3W[tid * 2 + j] : g2W[tid * 2 + (j - 2)];
        d_W2eff[tid * 4 + j] = ssc[tid] * w;
    }
    if (tid < 4) {
        float acc = (tid < 2) ? lin3b[tid] : 0.f;
        for (int k = 0; k < HCC; k++) {
            float w = (tid < 2) ? lin3W[k * 2 + tid] : g2W[k * 2 + (tid - 2)];
            acc += tsh[k] * w;
        }
        d_c2[tid] = acc;
    }
}

// Y2[N,4] = h1 @ W2eff + c2; also al2_s / al2_d. One warp per node.
__global__ void k_gemm2(const float* __restrict__ asrc, const float* __restrict__ adst) {
    __shared__ float Wsh[HCC * 4];
    int tid = threadIdx.x;
    for (int i = tid; i < HCC * 4; i += blockDim.x) Wsh[i] = d_W2eff[i];
    __syncthreads();
    int w = (blockIdx.x * blockDim.x + tid) >> 5;
    int lane = tid & 31;
    if (w >= NN) return;
    const float* hrow = d_h1 + (size_t)w * HCC;
    float a0 = 0.f, a1 = 0.f, a2 = 0.f, a3 = 0.f;
    #pragma unroll
    for (int j = 0; j < 8; j++) {
        int k = lane + 32 * j;
        float h = hrow[k];
        a0 += h * Wsh[k * 4 + 0];
        a1 += h * Wsh[k * 4 + 1];
        a2 += h * Wsh[k * 4 + 2];
        a3 += h * Wsh[k * 4 + 3];
    }
    a0 = warpSum(a0); a1 = warpSum(a1); a2 = warpSum(a2); a3 = warpSum(a3);
    if (lane == 0) {
        a0 += d_c2[0]; a1 += d_c2[1]; a2 += d_c2[2]; a3 += d_c2[3];
        d_Y2[w * 4 + 0] = a0;
        d_Y2[w * 4 + 1] = a1;
        d_Y2[w * 4 + 2] = a2;
        d_Y2[w * 4 + 3] = a3;
        d_als2[w] = a2 * asrc[0] + a3 * asrc[1];
        d_ald2[w] = a2 * adst[0] + a3 * adst[1];
    }
}

// layer-2 edge aggregation + final relu. One warp per dst node.
__global__ void k_edge2(const float* __restrict__ g2bias, float* __restrict__ out) {
    int w = (blockIdx.x * blockDim.x + threadIdx.x) >> 5;
    int lane = threadIdx.x & 31;
    if (w >= NN) return;
    int beg = d_rowptr[w], end = d_rowptr[w + 1];
    float a0 = 0.f, a1 = 0.f;
    if (end > beg) {
        float ad = d_ald2[w];
        float m = -1e30f;
        for (int i = beg + lane; i < end; i += 32) {
            float e = lrelu(d_als2[d_ssrc[i]] + ad);
            m = fmaxf(m, e);
        }
        m = warpMax(m);
        float ssum = 0.f;
        for (int i = beg + lane; i < end; i += 32) {
            float e = lrelu(d_als2[d_ssrc[i]] + ad);
            ssum += __expf(e - m);
        }
        float inv = 1.f / (warpSum(ssum) + 1e-16f);
        for (int i = beg + lane; i < end; i += 32) {
            int s = d_ssrc[i];
            float e = lrelu(d_als2[s] + ad);
            float wgt = __expf(e - m) * inv;
            a0 += d_Y2[s * 4 + 2] * wgt;
            a1 += d_Y2[s * 4 + 3] * wgt;
        }
        a0 = warpSum(a0);
        a1 = warpSum(a1);
    }
    if (lane == 0) {
        float v0 = d_Y2[w * 4 + 0] + g2bias[0] + a0;
        float v1 = d_Y2[w * 4 + 1] + g2bias[1] + a1;
        out[w * 2 + 0] = v0 > 0.f ? v0 : 0.f;
        out[w * 2 + 1] = v1 > 0.f ? v1 : 0.f;
    }
}

// ---------------- launch ----------------
extern "C" void kernel_launch(void* const* d_in, const int* in_sizes, int n_in,
                              void* d_out, int out_size) {
    const float* x       = (const float*)d_in[0];
    const void*  ei      = (const void*)d_in[1];
    const float* bn1_g   = (const float*)d_in[2];
    const float* bn1_b   = (const float*)d_in[3];
    const float* bn3_g   = (const float*)d_in[4];
    const float* bn3_b   = (const float*)d_in[5];
    const float* lin1_W  = (const float*)d_in[6];
    const float* lin1_b  = (const float*)d_in[7];
    const float* lin3_W  = (const float*)d_in[8];
    const float* lin3_b  = (const float*)d_in[9];
    const float* g1_W    = (const float*)d_in[10];
    const float* g1_asrc = (const float*)d_in[11];
    const float* g1_adst = (const float*)d_in[12];
    const float* g1_bias = (const float*)d_in[13];
    const float* g2_W    = (const float*)d_in[14];
    const float* g2_asrc = (const float*)d_in[15];
    const float* g2_adst = (const float*)d_in[16];
    const float* g2_bias = (const float*)d_in[17];
    float* out = (float*)d_out;

    const int warpsGrid = (NN * 32 + 255) / 256;   // 6250 blocks of 256 (warp/node)

    k_zero<<<(NN + 255) / 256, 256>>>();
    k_detect<<<784, 256>>>((const long long*)ei);
    k_decode<<<784, 256>>>(ei);
    k_colstats_x<<<512, 128>>>(x);
    k_hist<<<784, 256>>>();
    k_scan<<<1, 1024>>>();
    k_scatter<<<784, 256>>>();
    k_fold1<<<1, 512>>>(bn1_g, bn1_b, lin1_W, lin1_b, g1_W);
    dim3 g1grid(8, (NN + 63) / 64);
    k_gemm1<<<g1grid, 256>>>(x);
    k_alphas1<<<warpsGrid, 256>>>(g1_asrc, g1_adst);
    k_edge1<<<warpsGrid, 256>>>(g1_bias);
    k_colstats_h1<<<512, 256>>>();
    k_fold2<<<1, 256>>>(bn3_g, bn3_b, lin3_W, lin3_b, g2_W);
    k_gemm2<<<warpsGrid, 256>>>(g2_asrc, g2_adst);
    k_edge2<<<warpsGrid, 256>>>(g2_bias, out);
}

// round 3
// speedup vs baseline: 1.3292x; 1.3292x over previous
#include <cuda_runtime.h>
#include <cstdint>

#define NN 50000
#define FIN 128
#define HCC 256
#define EE 800000
#define BN_EPS 1e-5f

// ---------------- scratch (device globals; no allocation allowed) ----------------
__device__ __align__(16) float d_Y1lin[(size_t)NN * 256]; // lin1 part (pre-bias-combined via c1)
__device__ __align__(16) float d_HW[(size_t)NN * 256];    // h@g1_W (+c1 tail)
__device__ __align__(16) float d_h1[(size_t)NN * HCC];    // layer-1 output
__device__ __align__(16) float d_als1[NN * 4];
__device__ __align__(16) float d_ald1[NN * 4];
__device__ __align__(16) float d_Y2[NN * 4];
__device__ float d_als2[NN];
__device__ float d_ald2[NN];
__device__ int   d_src[EE];
__device__ int   d_dst[EE];
__device__ int   d_deg[NN];
__device__ int   d_rowptr[NN + 1];
__device__ int   d_wpos[NN];
__device__ int   d_ssrc[EE];
__device__ float d_sum1[FIN], d_sq1[FIN];
__device__ float d_sum3[HCC], d_sq3[HCC];
__device__ __align__(16) float d_W1eff[FIN * 512];
__device__ float d_c1[512];
__device__ float d_W2effT[4 * HCC];   // [c][k] transposed
__device__ float d_c2[4];
__device__ int   d_is64;

// ---------------- helpers ----------------
__device__ __forceinline__ float warpMax(float v) {
    #pragma unroll
    for (int o = 16; o; o >>= 1) v = fmaxf(v, __shfl_xor_sync(0xffffffffu, v, o));
    return v;
}
__device__ __forceinline__ float warpSum(float v) {
    #pragma unroll
    for (int o = 16; o; o >>= 1) v += __shfl_xor_sync(0xffffffffu, v, o);
    return v;
}
__device__ __forceinline__ float lrelu(float x) { return x > 0.f ? x : 0.2f * x; }
__device__ __forceinline__ float sel4(float a, float b, float c, float d, int h) {
    return h < 2 ? (h == 0 ? a : b) : (h == 2 ? c : d);
}

// ---------------- kernels ----------------
__global__ void k_zero() {
    int i = blockIdx.x * blockDim.x + threadIdx.x;
    if (i < NN) d_deg[i] = 0;
    if (i < FIN) { d_sum1[i] = 0.f; d_sq1[i] = 0.f; }
    if (i < HCC) { d_sum3[i] = 0.f; d_sq3[i] = 0.f; }
    if (i == 0) d_is64 = 1;
}

// dtype probe: int32 data viewed as int64 packs pairs -> huge values.
__global__ void k_detect(const long long* __restrict__ p) {
    int stride = gridDim.x * blockDim.x;
    for (int e = blockIdx.x * blockDim.x + threadIdx.x; e < EE; e += stride) {
        long long v = p[e];
        if (v < 0 || v >= NN) { d_is64 = 0; return; }
    }
}

// decode + degree histogram in one pass
__global__ void k_decode(const void* __restrict__ ei) {
    int stride = gridDim.x * blockDim.x;
    bool is64 = (d_is64 != 0);
    for (int e = blockIdx.x * blockDim.x + threadIdx.x; e < EE; e += stride) {
        int s, d;
        if (is64) {
            const long long* p = (const long long*)ei;
            s = (int)p[e]; d = (int)p[EE + e];
        } else {
            const int* p = (const int*)ei;
            s = p[e]; d = p[EE + e];
        }
        d_src[e] = (s >= 0 && s < NN) ? s : 0;
        if (d >= 0 && d < NN) { d_dst[e] = d; atomicAdd(&d_deg[d], 1); }
        else d_dst[e] = -1;
    }
}

// column mean/var stats for X [N,128] — warp per row, float4, block smem reduce
__global__ void k_colstats_x(const float* __restrict__ X) {
    __shared__ float s_s[FIN], s_q[FIN];
    int tid = threadIdx.x;                     // 256
    if (tid < FIN) { s_s[tid] = 0.f; s_q[tid] = 0.f; }
    __syncthreads();
    int lane = tid & 31;
    int nw = (gridDim.x * blockDim.x) >> 5;
    int gw = (blockIdx.x * blockDim.x + tid) >> 5;
    float s0 = 0, s1 = 0, s2 = 0, s3 = 0, q0 = 0, q1 = 0, q2 = 0, q3 = 0;
    for (int r = gw; r < NN; r += nw) {
        float4 v = *(const float4*)(X + (size_t)r * FIN + lane * 4);
        s0 += v.x; q0 += v.x * v.x;
        s1 += v.y; q1 += v.y * v.y;
        s2 += v.z; q2 += v.z * v.z;
        s3 += v.w; q3 += v.w * v.w;
    }
    atomicAdd(&s_s[lane * 4 + 0], s0); atomicAdd(&s_q[lane * 4 + 0], q0);
    atomicAdd(&s_s[lane * 4 + 1], s1); atomicAdd(&s_q[lane * 4 + 1], q1);
    atomicAdd(&s_s[lane * 4 + 2], s2); atomicAdd(&s_q[lane * 4 + 2], q2);
    atomicAdd(&s_s[lane * 4 + 3], s3); atomicAdd(&s_q[lane * 4 + 3], q3);
    __syncthreads();
    if (tid < FIN) { atomicAdd(&d_sum1[tid], s_s[tid]); atomicAdd(&d_sq1[tid], s_q[tid]); }
}

// column stats for h1 [N,256]
__global__ void k_colstats_h1() {
    __shared__ float s_s[HCC], s_q[HCC];
    int tid = threadIdx.x;                     // 256
    s_s[tid] = 0.f; s_q[tid] = 0.f;
    __syncthreads();
    int lane = tid & 31;
    int nw = (gridDim.x * blockDim.x) >> 5;
    int gw = (blockIdx.x * blockDim.x + tid) >> 5;
    float s[8] = {0, 0, 0, 0, 0, 0, 0, 0}, q[8] = {0, 0, 0, 0, 0, 0, 0, 0};
    for (int r = gw; r < NN; r += nw) {
        const float* row = d_h1 + (size_t)r * HCC;
        float4 v0 = *(const float4*)(row + lane * 4);
        float4 v1 = *(const float4*)(row + 128 + lane * 4);
        s[0] += v0.x; q[0] += v0.x * v0.x; s[1] += v0.y; q[1] += v0.y * v0.y;
        s[2] += v0.z; q[2] += v0.z * v0.z; s[3] += v0.w; q[3] += v0.w * v0.w;
        s[4] += v1.x; q[4] += v1.x * v1.x; s[5] += v1.y; q[5] += v1.y * v1.y;
        s[6] += v1.z; q[6] += v1.z * v1.z; s[7] += v1.w; q[7] += v1.w * v1.w;
    }
    #pragma unroll
    for (int i = 0; i < 4; i++) {
        atomicAdd(&s_s[lane * 4 + i], s[i]);       atomicAdd(&s_q[lane * 4 + i], q[i]);
        atomicAdd(&s_s[128 + lane * 4 + i], s[4 + i]); atomicAdd(&s_q[128 + lane * 4 + i], q[4 + i]);
    }
    __syncthreads();
    atomicAdd(&d_sum3[tid], s_s[tid]); atomicAdd(&d_sq3[tid], s_q[tid]);
}

__global__ void k_scan() {                    // single block, 1024 threads
    __shared__ int tots[1024];
    int t = threadIdx.x;
    const int per = (NN + 1023) / 1024;
    int beg = t * per, end = min(beg + per, NN);
    int s = 0;
    for (int i = beg; i < end; i++) s += d_deg[i];
    tots[t] = s;
    __syncthreads();
    for (int off = 1; off < 1024; off <<= 1) {
        int v = (t >= off) ? tots[t - off] : 0;
        __syncthreads();
        tots[t] += v;
        __syncthreads();
    }
    int prefix = (t == 0) ? 0 : tots[t - 1];
    for (int i = beg; i < end; i++) {
        int dv = d_deg[i];
        d_rowptr[i] = prefix;
        d_wpos[i] = prefix;
        prefix += dv;
    }
    if (t == 1023) d_rowptr[NN] = prefix;
}

__global__ void k_scatter() {
    int stride = gridDim.x * blockDim.x;
    for (int e = blockIdx.x * blockDim.x + threadIdx.x; e < EE; e += stride) {
        int dd = d_dst[e];
        if (dd >= 0) {
            int p = atomicAdd(&d_wpos[dd], 1);
            d_ssrc[p] = d_src[e];
        }
    }
}

// fold BN1 into [lin1_W | g1_W]
__global__ void k_fold1(const float* __restrict__ g, const float* __restrict__ b,
                        const float* __restrict__ lin1W, const float* __restrict__ lin1b,
                        const float* __restrict__ g1W) {
    __shared__ float ssc[FIN], tsh[FIN];
    int tid = threadIdx.x;                    // 512
    if (tid < FIN) {
        float mu  = d_sum1[tid] * (1.f / NN);
        float var = d_sq1[tid] * (1.f / NN) - mu * mu;
        float sc  = rsqrtf(var + BN_EPS) * g[tid];
        ssc[tid] = sc;
        tsh[tid] = b[tid] - mu * sc;
    }
    __syncthreads();
    int j = tid;
    float acc = (j < 256) ? lin1b[j] : 0.f;
    for (int k = 0; k < FIN; k++) {
        float w = (j < 256) ? lin1W[k * 256 + j] : g1W[k * 256 + (j - 256)];
        acc += tsh[k] * w;
    }
    d_c1[j] = acc;
    for (int idx = tid; idx < FIN * 512; idx += 512) {
        int k = idx >> 9, jj = idx & 511;
        float w = (jj < 256) ? lin1W[k * 256 + jj] : g1W[k * 256 + (jj - 256)];
        d_W1eff[idx] = ssc[k] * w;
    }
}

// Y1 = x @ W1eff + c1 : 128x128 tile, BK=16, 8x8 microtile, 256 threads.
// Block col0<256 -> d_Y1lin ; col0>=256 -> d_HW
__global__ void __launch_bounds__(256) k_gemm1(const float* __restrict__ A) {
    __shared__ float As[16][132];
    __shared__ float Bs[16][128];
    int tid = threadIdx.x;
    int row0 = blockIdx.y * 128, col0 = blockIdx.x * 128;
    int ty = tid >> 4, tx = tid & 15;
    float acc[8][8];
    #pragma unroll
    for (int u = 0; u < 8; u++)
        #pragma unroll
        for (int v = 0; v < 8; v++) acc[u][v] = 0.f;

    for (int k0 = 0; k0 < FIN; k0 += 16) {
        #pragma unroll
        for (int i = 0; i < 2; i++) {
            int f = tid + i * 256;
            int r = f >> 2, kq = f & 3;
            int gr = row0 + r;
            float4 v = make_float4(0.f, 0.f, 0.f, 0.f);
            if (gr < NN) v = *(const float4*)(A + (size_t)gr * FIN + k0 + kq * 4);
            As[kq * 4 + 0][r] = v.x;
            As[kq * 4 + 1][r] = v.y;
            As[kq * 4 + 2][r] = v.z;
            As[kq * 4 + 3][r] = v.w;
        }
        #pragma unroll
        for (int i = 0; i < 2; i++) {
            int f = tid + i * 256;
            int kr = f >> 5, c4 = f & 31;
            *(float4*)(&Bs[kr][c4 * 4]) = *(const float4*)(d_W1eff + (k0 + kr) * 512 + col0 + c4 * 4);
        }
        __syncthreads();
        #pragma unroll
        for (int kk = 0; kk < 16; kk++) {
            float a[8], bb[8];
            *(float4*)(a)     = *(const float4*)(&As[kk][ty * 8]);
            *(float4*)(a + 4) = *(const float4*)(&As[kk][ty * 8 + 4]);
            *(float4*)(bb)    = *(const float4*)(&Bs[kk][tx * 8]);
            *(float4*)(bb + 4)= *(const float4*)(&Bs[kk][tx * 8 + 4]);
            #pragma unroll
            for (int u = 0; u < 8; u++)
                #pragma unroll
                for (int v = 0; v < 8; v++) acc[u][v] += a[u] * bb[v];
        }
        __syncthreads();
    }
    float* dst = (col0 < 256) ? d_Y1lin : d_HW;
    int cbase = (col0 < 256) ? col0 : (col0 - 256);
    float cb[8];
    #pragma unroll
    for (int v = 0; v < 8; v++) cb[v] = d_c1[col0 + tx * 8 + v];
    #pragma unroll
    for (int u = 0; u < 8; u++) {
        int gr = row0 + ty * 8 + u;
        if (gr < NN) {
            #pragma unroll
            for (int v = 0; v < 8; v += 4) {
                float4 o;
                o.x = acc[u][v + 0] + cb[v + 0];
                o.y = acc[u][v + 1] + cb[v + 1];
                o.z = acc[u][v + 2] + cb[v + 2];
                o.w = acc[u][v + 3] + cb[v + 3];
                *(float4*)(dst + (size_t)gr * 256 + cbase + tx * 8 + v) = o;
            }
        }
    }
}

// attention logit projections (vectorized: lane covers 8 consecutive cols = one head chunk)
__global__ void k_alphas1(const float* __restrict__ asrc, const float* __restrict__ adst) {
    int w = (blockIdx.x * blockDim.x + threadIdx.x) >> 5;
    int lane = threadIdx.x & 31;
    if (w >= NN) return;
    const float* hw = d_HW + (size_t)w * 256;
    float4 h0 = *(const float4*)(hw + lane * 8);
    float4 h1 = *(const float4*)(hw + lane * 8 + 4);
    float4 a0 = *(const float4*)(asrc + lane * 8);
    float4 a1 = *(const float4*)(asrc + lane * 8 + 4);
    float4 b0 = *(const float4*)(adst + lane * 8);
    float4 b1 = *(const float4*)(adst + lane * 8 + 4);
    float s = h0.x * a0.x + h0.y * a0.y + h0.z * a0.z + h0.w * a0.w
            + h1.x * a1.x + h1.y * a1.y + h1.z * a1.z + h1.w * a1.w;
    float d = h0.x * b0.x + h0.y * b0.y + h0.z * b0.z + h0.w * b0.w
            + h1.x * b1.x + h1.y * b1.y + h1.z * b1.z + h1.w * b1.w;
    #pragma unroll
    for (int o = 1; o < 8; o <<= 1) {
        s += __shfl_xor_sync(0xffffffffu, s, o);
        d += __shfl_xor_sync(0xffffffffu, d, o);
    }
    if ((lane & 7) == 0) {
        d_als1[w * 4 + (lane >> 3)] = s;
        d_ald1[w * 4 + (lane >> 3)] = d;
    }
}

// layer-1 edge aggregation + combine + relu -> h1. One warp per dst node, no atomics.
__global__ void k_edge1(const float* __restrict__ g1bias) {
    int w = (blockIdx.x * blockDim.x + threadIdx.x) >> 5;
    int lane = threadIdx.x & 31;
    if (w >= NN) return;
    int beg = d_rowptr[w], end = d_rowptr[w + 1];
    int h = lane >> 3;                         // head owned by this lane (cols lane*8..+7)
    float acc[8];
    #pragma unroll
    for (int j = 0; j < 8; j++) acc[j] = 0.f;

    if (end > beg) {
        float4 adv = *(const float4*)(d_ald1 + w * 4);
        // pass 1: per-head max
        float m0 = -1e30f, m1 = -1e30f, m2 = -1e30f, m3 = -1e30f;
        for (int i = beg + lane; i < end; i += 32) {
            int s = d_ssrc[i];
            float4 av = *(const float4*)(d_als1 + s * 4);
            m0 = fmaxf(m0, lrelu(av.x + adv.x));
            m1 = fmaxf(m1, lrelu(av.y + adv.y));
            m2 = fmaxf(m2, lrelu(av.z + adv.z));
            m3 = fmaxf(m3, lrelu(av.w + adv.w));
        }
        m0 = warpMax(m0); m1 = warpMax(m1); m2 = warpMax(m2); m3 = warpMax(m3);
        // pass 2: per-head sum
        float s0 = 0.f, s1 = 0.f, s2 = 0.f, s3 = 0.f;
        for (int i = beg + lane; i < end; i += 32) {
            int s = d_ssrc[i];
            float4 av = *(const float4*)(d_als1 + s * 4);
            s0 += __expf(lrelu(av.x + adv.x) - m0);
            s1 += __expf(lrelu(av.y + adv.y) - m1);
            s2 += __expf(lrelu(av.z + adv.z) - m2);
            s3 += __expf(lrelu(av.w + adv.w) - m3);
        }
        s0 = warpSum(s0); s1 = warpSum(s1); s2 = warpSum(s2); s3 = warpSum(s3);
        // per-lane scalars for owned head
        float adh  = sel4(adv.x, adv.y, adv.z, adv.w, h);
        float mh   = sel4(m0, m1, m2, m3, h);
        float invh = 1.f / (sel4(s0, s1, s2, s3, h) + 1e-16f);
        // pass 3: weighted accumulation (whole warp per edge, 2x LDG.128/lane)
        #pragma unroll 2
        for (int i = beg; i < end; i++) {
            int s = d_ssrc[i];
            float avh = sel4(d_als1[s * 4 + 0], d_als1[s * 4 + 1],
                             d_als1[s * 4 + 2], d_als1[s * 4 + 3], h);
            float wgt = __expf(lrelu(avh + adh) - mh) * invh;
            const float* hwrow = d_HW + (size_t)s * 256 + lane * 8;
            float4 p0 = *(const float4*)(hwrow);
            float4 p1 = *(const float4*)(hwrow + 4);
            acc[0] += p0.x * wgt; acc[1] += p0.y * wgt;
            acc[2] += p0.z * wgt; acc[3] += p0.w * wgt;
            acc[4] += p1.x * wgt; acc[5] += p1.y * wgt;
            acc[6] += p1.z * wgt; acc[7] += p1.w * wgt;
        }
    }
    const float* linrow = d_Y1lin + (size_t)w * 256 + lane * 8;
    float4 l0 = *(const float4*)(linrow);
    float4 l1 = *(const float4*)(linrow + 4);
    float4 g0 = *(const float4*)(g1bias + lane * 8);
    float4 g1v = *(const float4*)(g1bias + lane * 8 + 4);
    float4 o0, o1;
    o0.x = fmaxf(acc[0] + l0.x + g0.x, 0.f);
    o0.y = fmaxf(acc[1] + l0.y + g0.y, 0.f);
    o0.z = fmaxf(acc[2] + l0.z + g0.z, 0.f);
    o0.w = fmaxf(acc[3] + l0.w + g0.w, 0.f);
    o1.x = fmaxf(acc[4] + l1.x + g1v.x, 0.f);
    o1.y = fmaxf(acc[5] + l1.y + g1v.y, 0.f);
    o1.z = fmaxf(acc[6] + l1.z + g1v.z, 0.f);
    o1.w = fmaxf(acc[7] + l1.w + g1v.w, 0.f);
    float* orow = d_h1 + (size_t)w * HCC + lane * 8;
    *(float4*)(orow) = o0;
    *(float4*)(orow + 4) = o1;
}

// fold BN3 into [lin3_W | g2_W] (transposed output)
__global__ void k_fold2(const float* __restrict__ g, const float* __restrict__ b,
                        const float* __restrict__ lin3W, const float* __restrict__ lin3b,
                        const float* __restrict__ g2W) {
    __shared__ float ssc[HCC], tsh[HCC];
    int tid = threadIdx.x;                    // 256
    float mu  = d_sum3[tid] * (1.f / NN);
    float var = d_sq3[tid] * (1.f / NN) - mu * mu;
    float sc  = rsqrtf(var + BN_EPS) * g[tid];
    ssc[tid] = sc;
    tsh[tid] = b[tid] - mu * sc;
    __syncthreads();
    #pragma unroll
    for (int j = 0; j < 4; j++) {
        float w = (j < 2) ? lin3W[tid * 2 + j] : g2W[tid * 2 + (j - 2)];
        d_W2effT[j * HCC + tid] = ssc[tid] * w;
    }
    if (tid < 4) {
        float acc = (tid < 2) ? lin3b[tid] : 0.f;
        for (int k = 0; k < HCC; k++) {
            float w = (tid < 2) ? lin3W[k * 2 + tid] : g2W[k * 2 + (tid - 2)];
            acc += tsh[k] * w;
        }
        d_c2[tid] = acc;
    }
}

// Y2[N,4] = h1 @ W2eff + c2; also al2_s / al2_d. One warp per node.
__global__ void k_gemm2(const float* __restrict__ asrc, const float* __restrict__ adst) {
    __shared__ float Wsh[4 * HCC];
    int tid = threadIdx.x;
    for (int i = tid; i < 4 * HCC; i += blockDim.x) Wsh[i] = d_W2effT[i];
    __syncthreads();
    int w = (blockIdx.x * blockDim.x + tid) >> 5;
    int lane = tid & 31;
    if (w >= NN) return;
    const float* hrow = d_h1 + (size_t)w * HCC;
    float a0 = 0.f, a1 = 0.f, a2 = 0.f, a3 = 0.f;
    #pragma unroll
    for (int j = 0; j < 8; j++) {
        int k = lane + 32 * j;
        float hv = hrow[k];
        a0 += hv * Wsh[k];
        a1 += hv * Wsh[HCC + k];
        a2 += hv * Wsh[2 * HCC + k];
        a3 += hv * Wsh[3 * HCC + k];
    }
    a0 = warpSum(a0); a1 = warpSum(a1); a2 = warpSum(a2); a3 = warpSum(a3);
    if (lane == 0) {
        a0 += d_c2[0]; a1 += d_c2[1]; a2 += d_c2[2]; a3 += d_c2[3];
        d_Y2[w * 4 + 0] = a0;
        d_Y2[w * 4 + 1] = a1;
        d_Y2[w * 4 + 2] = a2;
        d_Y2[w * 4 + 3] = a3;
        d_als2[w] = a2 * asrc[0] + a3 * asrc[1];
        d_ald2[w] = a2 * adst[0] + a3 * adst[1];
    }
}

// layer-2 edge aggregation + final relu. One warp per dst node.
__global__ void k_edge2(const float* __restrict__ g2bias, float* __restrict__ out) {
    int w = (blockIdx.x * blockDim.x + threadIdx.x) >> 5;
    int lane = threadIdx.x & 31;
    if (w >= NN) return;
    int beg = d_rowptr[w], end = d_rowptr[w + 1];
    float a0 = 0.f, a1 = 0.f;
    if (end > beg) {
        float ad = d_ald2[w];
        float m = -1e30f;
        for (int i = beg + lane; i < end; i += 32) {
            m = fmaxf(m, lrelu(d_als2[d_ssrc[i]] + ad));
        }
        m = warpMax(m);
        float ssum = 0.f;
        for (int i = beg + lane; i < end; i += 32) {
            ssum += __expf(lrelu(d_als2[d_ssrc[i]] + ad) - m);
        }
        float inv = 1.f / (warpSum(ssum) + 1e-16f);
        for (int i = beg + lane; i < end; i += 32) {
            int s = d_ssrc[i];
            float wgt = __expf(lrelu(d_als2[s] + ad) - m) * inv;
            a0 += d_Y2[s * 4 + 2] * wgt;
            a1 += d_Y2[s * 4 + 3] * wgt;
        }
        a0 = warpSum(a0);
        a1 = warpSum(a1);
    }
    if (lane == 0) {
        float v0 = d_Y2[w * 4 + 0] + g2bias[0] + a0;
        float v1 = d_Y2[w * 4 + 1] + g2bias[1] + a1;
        out[w * 2 + 0] = v0 > 0.f ? v0 : 0.f;
        out[w * 2 + 1] = v1 > 0.f ? v1 : 0.f;
    }
}

// ---------------- launch ----------------
extern "C" void kernel_launch(void* const* d_in, const int* in_sizes, int n_in,
                              void* d_out, int out_size) {
    const float* x       = (const float*)d_in[0];
    const void*  ei      = (const void*)d_in[1];
    const float* bn1_g   = (const float*)d_in[2];
    const float* bn1_b   = (const float*)d_in[3];
    const float* bn3_g   = (const float*)d_in[4];
    const float* bn3_b   = (const float*)d_in[5];
    const float* lin1_W  = (const float*)d_in[6];
    const float* lin1_b  = (const float*)d_in[7];
    const float* lin3_W  = (const float*)d_in[8];
    const float* lin3_b  = (const float*)d_in[9];
    const float* g1_W    = (const float*)d_in[10];
    const float* g1_asrc = (const float*)d_in[11];
    const float* g1_adst = (const float*)d_in[12];
    const float* g1_bias = (const float*)d_in[13];
    const float* g2_W    = (const float*)d_in[14];
    const float* g2_asrc = (const float*)d_in[15];
    const float* g2_adst = (const float*)d_in[16];
    const float* g2_bias = (const float*)d_in[17];
    float* out = (float*)d_out;

    const int warpsGrid = (NN * 32 + 255) / 256;   // 6250 blocks (warp/node)

    k_zero<<<(NN + 255) / 256, 256>>>();
    k_detect<<<784, 256>>>((const long long*)ei);
    k_decode<<<784, 256>>>(ei);
    k_colstats_x<<<512, 256>>>(x);
    k_scan<<<1, 1024>>>();
    k_scatter<<<784, 256>>>();
    k_fold1<<<1, 512>>>(bn1_g, bn1_b, lin1_W, lin1_b, g1_W);
    dim3 g1grid(4, (NN + 127) / 128);
    k_gemm1<<<g1grid, 256>>>(x);
    k_alphas1<<<warpsGrid, 256>>>(g1_asrc, g1_adst);
    k_edge1<<<warpsGrid, 256>>>(g1_bias);
    k_colstats_h1<<<512, 256>>>();
    k_fold2<<<1, 256>>>(bn3_g, bn3_b, lin3_W, lin3_b, g2_W);
    k_gemm2<<<warpsGrid, 256>>>(g2_asrc, g2_adst);
    k_edge2<<<warpsGrid, 256>>>(g2_bias, out);
}